// round 17
// baseline (speedup 1.0000x reference)
#include <cuda_runtime.h>
#include <cuda_fp16.h>
#include <math.h>
#include <stdint.h>

// Problem constants
#define T_TOK 4096      // B*L tokens
#define Dd    1024      // model dim
#define Hh    512       // expert hidden
#define Ee    16        // num experts
#define Ss    2048      // shared expert hidden
#define TOPK  2

// ---------------- device scratch (no allocations allowed) ----------------
__device__ uint32_t xs16[(size_t)T_TOK * Dd / 2];
__device__ uint32_t w1s[(size_t)Ee * Hh * Dd / 2];
__device__ uint32_t w2s[(size_t)Ee * Dd * Hh / 2];
__device__ uint32_t s1s[(size_t)Ss * Dd / 2];
__device__ uint32_t s2s[(size_t)Ss * Dd / 2];
__device__ uint32_t s3s[(size_t)Dd * Ss / 2];
__device__ uint32_t g16[(size_t)T_TOK * Ss / 2];
__device__ uint32_t h16[(size_t)T_TOK * TOPK * Hh / 2];
__device__ int   d_top_idx[T_TOK * TOPK];
__device__ float d_top_w[T_TOK * TOPK];
__device__ int   d_offsets[Ee + 1];
__device__ int   d_perm[T_TOK * TOPK];

__device__ __forceinline__ float silu_f(float v) { return v / (1.0f + expf(-v)); }

__device__ __forceinline__ uint32_t smem_u32(const void* p) {
    uint32_t a;
    asm("{ .reg .u64 t; cvta.to.shared.u64 t, %1; cvt.u32.u64 %0, t; }" : "=r"(a) : "l"(p));
    return a;
}
__device__ __forceinline__ uint32_t pack2_single(float a, float b) {
    __half2 h = __floats2half2_rn(a, b);
    return *(uint32_t*)&h;
}

__device__ __forceinline__ void ldsm_x4(uint32_t* r, uint32_t addr) {
    asm volatile("ldmatrix.sync.aligned.m8n8.x4.shared.b16 {%0,%1,%2,%3}, [%4];"
        : "=r"(r[0]), "=r"(r[1]), "=r"(r[2]), "=r"(r[3]) : "r"(addr));
}
__device__ __forceinline__ void ldsm_x2(uint32_t* r, uint32_t addr) {
    asm volatile("ldmatrix.sync.aligned.m8n8.x2.shared.b16 {%0,%1}, [%2];"
        : "=r"(r[0]), "=r"(r[1]) : "r"(addr));
}
__device__ __forceinline__ void mma16816(float* c, const uint32_t* a, const uint32_t* b) {
    asm volatile(
        "mma.sync.aligned.m16n8k16.row.col.f32.f16.f16.f32 "
        "{%0,%1,%2,%3}, {%4,%5,%6,%7}, {%8,%9}, {%0,%1,%2,%3};"
        : "+f"(c[0]), "+f"(c[1]), "+f"(c[2]), "+f"(c[3])
        : "r"(a[0]), "r"(a[1]), "r"(a[2]), "r"(a[3]), "r"(b[0]), "r"(b[1]));
}

__device__ __forceinline__ void cp16(uint32_t dst, const void* src, int sz) {
    asm volatile("cp.async.cg.shared.global [%0], [%1], 16, %2;"
                 :: "r"(dst), "l"(src), "r"(sz) : "memory");
}
#define CP_COMMIT() asm volatile("cp.async.commit_group;" ::: "memory")
#define CP_WAIT0()  asm volatile("cp.async.wait_group 0;" ::: "memory")
#define CP_WAIT1()  asm volatile("cp.async.wait_group 1;" ::: "memory")

// K-chunk = 64 fp16 (128B data + 16B pad = 144B row stride).
// Per stage: A = 128x144 = 18432B @0, B @18432. Stage = 36864. 3 stages = 110592.
#define ROWB        144
#define A_BYTES     18432
#define STAGE_BYTES 36864
#define SMEM_BYTES  110592

// ====== GEMM core: 128x128 tile, 8 warps (2x4), 64x32 warp tile ======
// K-chunks of 64, 3-stage cp.async, fragment double-buffer across s-steps.
template <int NC, typename FE>
__device__ __forceinline__ void gemm_core(
    int tid, char* smem,
    const char* aSrc, int szA,
    const char* bSrc, FE epi)
{
    const int lane  = tid & 31;
    const int wid   = tid >> 5;
    const int warpM = wid >> 2;
    const int warpN = wid & 3;
    uint32_t sb = smem_u32(smem);
    const int lr = tid >> 1;
    uint32_t dstBase = sb + (uint32_t)(lr * ROWB + (tid & 1) * 64);

    float acc[4][4][4];
    #pragma unroll
    for (int i = 0; i < 4; i++)
        #pragma unroll
        for (int t = 0; t < 4; t++)
            #pragma unroll
            for (int r = 0; r < 4; r++) acc[i][t][r] = 0.f;

    auto issue = [&](int c) {
        uint32_t d = dstBase + (uint32_t)(c % 3) * (uint32_t)STAGE_BYTES;
        const char* pA = aSrc + (size_t)c * 128;
        const char* pB = bSrc + (size_t)c * 128;
        #pragma unroll
        for (int j = 0; j < 4; j++) {
            cp16(d + j * 16,           pA + j * 16, szA);
            cp16(d + A_BYTES + j * 16, pB + j * 16, 16);
        }
    };

    issue(0); CP_COMMIT();
    if (NC > 1) { issue(1); CP_COMMIT(); }

    const uint32_t arow  = (uint32_t)((warpM * 64 + (lane & 15)) * ROWB);
    const uint32_t brow  = (uint32_t)((warpN * 32 + (lane & 7)) * ROWB);
    const uint32_t akoff = (uint32_t)(((lane >> 4) & 1) * 16);
    const uint32_t bkoff = (uint32_t)(((lane >> 3) & 1) * 16);

    uint32_t af[2][4][4], bf[2][4][2];

    #pragma unroll 1
    for (int c = 0; c < NC; c++) {
        if (c + 1 < NC) CP_WAIT1(); else CP_WAIT0();
        __syncthreads();
        uint32_t bufb = sb + (uint32_t)(c % 3) * (uint32_t)STAGE_BYTES;
        uint32_t akb = bufb + arow + akoff;
        uint32_t bkb = bufb + A_BYTES + brow + bkoff;
        // load s=0 fragments
        #pragma unroll
        for (int i = 0; i < 4; i++) ldsm_x4(af[0][i], akb + (uint32_t)(i * 16 * ROWB));
        #pragma unroll
        for (int t = 0; t < 4; t++) ldsm_x2(bf[0][t], bkb + (uint32_t)(t * 8 * ROWB));
        #pragma unroll
        for (int s = 0; s < 4; s++) {
            int cur = s & 1;
            if (s < 3) {
                int nxt = (s + 1) & 1;
                uint32_t ko = (uint32_t)((s + 1) * 32);
                #pragma unroll
                for (int i = 0; i < 4; i++) ldsm_x4(af[nxt][i], akb + ko + (uint32_t)(i * 16 * ROWB));
                #pragma unroll
                for (int t = 0; t < 4; t++) ldsm_x2(bf[nxt][t], bkb + ko + (uint32_t)(t * 8 * ROWB));
            }
            #pragma unroll
            for (int i = 0; i < 4; i++)
                #pragma unroll
                for (int t = 0; t < 4; t++) mma16816(acc[i][t], af[cur][i], bf[cur][t]);
        }
        if (c + 2 < NC) { issue(c + 2); CP_COMMIT(); }
    }
    epi(acc, warpM, warpN, lane);
}

// ---------------- fused prologue: router + out-zero + operand split ----------------
#define N2_X   (T_TOK * Dd / 2)
#define N2_W1  (Ee * Hh * Dd / 2)
#define N2_W2  (Ee * Dd * Hh / 2)
#define N2_S1  (Ss * Dd / 2)
#define N2_S2  (Ss * Dd / 2)
#define N2_S3  (Dd * Ss / 2)
#define N2_TOT (N2_X + N2_W1 + N2_W2 + N2_S1 + N2_S2 + N2_S3)

#define NB_ROUTER (T_TOK / 8)
#define NB_ZERO   ((T_TOK * Dd / 4) / 256)
#define NB_SPLIT  ((N2_TOT + 255) / 256)
#define NB_PRE    (NB_ROUTER + NB_ZERO + NB_SPLIT)

__global__ void __launch_bounds__(256) pre_kernel(
    const float* __restrict__ x,  const float* __restrict__ gw,
    const float* __restrict__ w1, const float* __restrict__ w2,
    const float* __restrict__ sfc1, const float* __restrict__ sfc2,
    const float* __restrict__ sfc3, float* __restrict__ out)
{
    int b = blockIdx.x;
    int tid = threadIdx.x;
    if (b < NB_ROUTER) {
        int warp = tid >> 5;
        int lane = tid & 31;
        int t = b * 8 + warp;
        const float* xr = x + (size_t)t * Dd;
        float xv[32];
        #pragma unroll
        for (int j = 0; j < 32; j++) xv[j] = xr[lane + 32 * j];
        float logits[Ee];
        #pragma unroll 1
        for (int e = 0; e < Ee; e++) {
            const float* w = gw + (size_t)e * Dd;
            float p = 0.0f;
            #pragma unroll
            for (int j = 0; j < 32; j++) p += xv[j] * w[lane + 32 * j];
            #pragma unroll
            for (int o = 16; o; o >>= 1) p += __shfl_down_sync(0xffffffffu, p, o);
            if (lane == 0) logits[e] = p;
        }
        if (lane == 0) {
            int i0 = 0; float v0 = logits[0];
            #pragma unroll
            for (int e = 1; e < Ee; e++) if (logits[e] > v0) { v0 = logits[e]; i0 = e; }
            int i1 = -1; float v1 = -3.0e38f;
            #pragma unroll
            for (int e = 0; e < Ee; e++) if (e != i0 && logits[e] > v1) { v1 = logits[e]; i1 = e; }
            float ex = expf(v1 - v0);
            d_top_idx[2 * t]     = i0;
            d_top_idx[2 * t + 1] = i1;
            d_top_w[2 * t]       = 1.0f / (1.0f + ex);
            d_top_w[2 * t + 1]   = ex / (1.0f + ex);
        }
        return;
    }
    b -= NB_ROUTER;
    if (b < NB_ZERO) {
        int i = b * 256 + tid;
        ((float4*)out)[i] = make_float4(0.f, 0.f, 0.f, 0.f);
        return;
    }
    b -= NB_ZERO;
    int i = b * 256 + tid;
    if (i >= N2_TOT) return;
    const float* src;
    uint32_t* dst;
    int j = i;
    if (j < N2_X)                     { src = x;    dst = xs16; }
    else if ((j -= N2_X)  < N2_W1)    { src = w1;   dst = w1s; }
    else if ((j -= N2_W1) < N2_W2)    { src = w2;   dst = w2s; }
    else if ((j -= N2_W2) < N2_S1)    { src = sfc1; dst = s1s; }
    else if ((j -= N2_S1) < N2_S2)    { src = sfc2; dst = s2s; }
    else       { j -= N2_S2;            src = sfc3; dst = s3s; }
    float2 v = ((const float2*)src)[j];
    dst[j] = pack2_single(v.x, v.y);
}

// ---------------- scan + scatter (single block) ----------------
__global__ void scan_scatter_kernel()
{
    __shared__ int cnt[Ee];
    __shared__ int off[Ee];
    int tid = threadIdx.x;
    if (tid < Ee) cnt[tid] = 0;
    __syncthreads();
    for (int s = tid; s < T_TOK * TOPK; s += blockDim.x)
        atomicAdd(&cnt[d_top_idx[s]], 1);
    __syncthreads();
    if (tid == 0) {
        int o = 0;
        for (int e = 0; e < Ee; e++) { off[e] = o; d_offsets[e] = o; o += cnt[e]; }
        d_offsets[Ee] = o;
    }
    __syncthreads();
    if (tid < Ee) cnt[tid] = off[tid];
    __syncthreads();
    for (int s = tid; s < T_TOK * TOPK; s += blockDim.x) {
        int e = d_top_idx[s];
        int p = atomicAdd(&cnt[e], 1);
        d_perm[p] = s;
    }
}

// ================= merged GEMM kernels =================

// kernel A: blocks [0,1024) = shared GEMM1 ; blocks [1024,1024+4096) = MoE GEMM1
#define A_S1_BLOCKS 1024
#define A_MOE_BLOCKS (4 * 64 * Ee)
__global__ void __launch_bounds__(256, 2) gemmA_mm()
{
    extern __shared__ char smem[];
    int b = blockIdx.x;
    int tid = threadIdx.x;
    int lr = tid >> 1, hb = (tid & 1) * 64;

    if (b < A_S1_BLOCKS) {
        int c0g  = (b & 31) * 64;
        int row0 = (b >> 5) * 128;
        const char* aSrc = (const char*)xs16 + (size_t)(row0 + lr) * (Dd * 2) + hb;
        int q = lr >> 3, nn = lr & 7;
        size_t brow = (size_t)(c0g + (q >> 1) * 8 + nn) * (Dd * 2) + hb;
        const char* bSrc = (const char*)((q & 1) ? s2s : s1s) + brow;

        auto epi = [=](float acc[4][4][4], int warpM, int warpN, int lane) {
            int gid = lane >> 2, tig = lane & 3;
            #pragma unroll
            for (int i = 0; i < 4; i++) {
                int m = row0 + warpM * 64 + i * 16 + gid;
                #pragma unroll
                for (int j = 0; j < 2; j++) {
                    int col = c0g + (warpN * 2 + j) * 8 + tig * 2;
                    size_t idx0 = (size_t)m * (Ss / 2) + (col >> 1);
                    g16[idx0] = pack2_single(silu_f(acc[i][2*j][0]) * acc[i][2*j+1][0],
                                             silu_f(acc[i][2*j][1]) * acc[i][2*j+1][1]);
                    size_t idx1 = (size_t)(m + 8) * (Ss / 2) + (col >> 1);
                    g16[idx1] = pack2_single(silu_f(acc[i][2*j][2]) * acc[i][2*j+1][2],
                                             silu_f(acc[i][2*j][3]) * acc[i][2*j+1][3]);
                }
            }
        };
        gemm_core<Dd / 64>(tid, smem, aSrc, 16, bSrc, epi);
    } else {
        int b2 = b - A_S1_BLOCKS;
        int col0 = (b2 & 3) * 128;
        int rest = b2 >> 2;
        int m0 = (rest & 63) * 128;
        int e = rest >> 6;
        int Ms = d_offsets[e], Me = d_offsets[e + 1];
        int M = Me - Ms;
        if (m0 >= M) return;

        int mrow = m0 + lr;
        bool okA = (mrow < M);
        int tok = okA ? (d_perm[Ms + mrow] >> 1) : 0;
        const char* aSrc = (const char*)xs16 + (size_t)tok * (Dd * 2) + hb;
        const char* bSrc = (const char*)w1s + ((size_t)e * Hh + col0 + lr) * (Dd * 2) + hb;

        auto epi = [=](float acc[4][4][4], int warpM, int warpN, int lane) {
            int gid = lane >> 2, tig = lane & 3;
            #pragma unroll
            for (int i = 0; i < 4; i++) {
                int mb = m0 + warpM * 64 + i * 16 + gid;
                #pragma unroll
                for (int t = 0; t < 4; t++) {
                    int col = col0 + warpN * 32 + t * 8 + tig * 2;
                    if (mb < M) {
                        size_t idx = (size_t)(Ms + mb) * (Hh / 2) + (col >> 1);
                        h16[idx] = pack2_single(silu_f(acc[i][t][0]), silu_f(acc[i][t][1]));
                    }
                    if (mb + 8 < M) {
                        size_t idx = (size_t)(Ms + mb + 8) * (Hh / 2) + (col >> 1);
                        h16[idx] = pack2_single(silu_f(acc[i][t][2]), silu_f(acc[i][t][3]));
                    }
                }
            }
        };
        gemm_core<Dd / 64>(tid, smem, aSrc, okA ? 16 : 0, bSrc, epi);
    }
}

// kernel B: blocks [0,256) = shared GEMM2 ; blocks [256,256+8192) = MoE GEMM2 (both atomic)
#define B_S2_BLOCKS 256
#define B_MOE_BLOCKS (8 * 64 * Ee)
__global__ void __launch_bounds__(256, 2) gemmB_mm(float* __restrict__ out)
{
    extern __shared__ char smem[];
    int b = blockIdx.x;
    int tid = threadIdx.x;
    int lr = tid >> 1, hb = (tid & 1) * 64;

    if (b < B_S2_BLOCKS) {
        int col0 = (b & 7) * 128;
        int row0 = (b >> 3) * 128;
        const char* aSrc = (const char*)g16 + (size_t)(row0 + lr) * (Ss * 2) + hb;
        const char* bSrc = (const char*)s3s + (size_t)(col0 + lr) * (Ss * 2) + hb;

        auto epi = [=](float acc[4][4][4], int warpM, int warpN, int lane) {
            int gid = lane >> 2, tig = lane & 3;
            #pragma unroll
            for (int i = 0; i < 4; i++) {
                int m = row0 + warpM * 64 + i * 16 + gid;
                #pragma unroll
                for (int t = 0; t < 4; t++) {
                    int col = col0 + warpN * 32 + t * 8 + tig * 2;
                    float* d0 = out + (size_t)m * Dd + col;
                    float* d1 = out + (size_t)(m + 8) * Dd + col;
                    atomicAdd(d0,     acc[i][t][0]);
                    atomicAdd(d0 + 1, acc[i][t][1]);
                    atomicAdd(d1,     acc[i][t][2]);
                    atomicAdd(d1 + 1, acc[i][t][3]);
                }
            }
        };
        gemm_core<Ss / 64>(tid, smem, aSrc, 16, bSrc, epi);
    } else {
        int b2 = b - B_S2_BLOCKS;
        int col0 = (b2 & 7) * 128;
        int rest = b2 >> 3;
        int m0 = (rest & 63) * 128;
        int e = rest >> 6;
        int Ms = d_offsets[e], Me = d_offsets[e + 1];
        int M = Me - Ms;
        if (m0 >= M) return;

        int mrow = m0 + lr;
        bool okA = (mrow < M);
        const char* aSrc = (const char*)h16 + (size_t)(Ms + (okA ? mrow : 0)) * (Hh * 2) + hb;
        const char* bSrc = (const char*)w2s + ((size_t)e * Dd + col0 + lr) * (Hh * 2) + hb;

        auto epi = [=](float acc[4][4][4], int warpM, int warpN, int lane) {
            int gid = lane >> 2, tig = lane & 3;
            #pragma unroll
            for (int i = 0; i < 4; i++) {
                int mb = m0 + warpM * 64 + i * 16 + gid;
                #pragma unroll
                for (int t = 0; t < 4; t++) {
                    int col = col0 + warpN * 32 + t * 8 + tig * 2;
                    if (mb < M) {
                        int slot = d_perm[Ms + mb];
                        float wk = d_top_w[slot];
                        float* d = out + (size_t)(slot >> 1) * Dd + col;
                        atomicAdd(d,     wk * acc[i][t][0]);
                        atomicAdd(d + 1, wk * acc[i][t][1]);
                    }
                    if (mb + 8 < M) {
                        int slot = d_perm[Ms + mb + 8];
                        float wk = d_top_w[slot];
                        float* d = out + (size_t)(slot >> 1) * Dd + col;
                        atomicAdd(d,     wk * acc[i][t][2]);
                        atomicAdd(d + 1, wk * acc[i][t][3]);
                    }
                }
            }
        };
        gemm_core<Hh / 64>(tid, smem, aSrc, okA ? 16 : 0, bSrc, epi);
    }
}

// ---------------- launch ----------------
extern "C" void kernel_launch(void* const* d_in, const int* in_sizes, int n_in,
                              void* d_out, int out_size)
{
    const float* x     = (const float*)d_in[0];
    const float* gatew = (const float*)d_in[1];
    const float* w1    = (const float*)d_in[2];
    const float* w2    = (const float*)d_in[3];
    const float* sfc1  = (const float*)d_in[4];
    const float* sfc2  = (const float*)d_in[5];
    const float* sfc3  = (const float*)d_in[6];
    float* out = (float*)d_out;

    cudaFuncSetAttribute(gemmA_mm, cudaFuncAttributeMaxDynamicSharedMemorySize, SMEM_BYTES);
    cudaFuncSetAttribute(gemmB_mm, cudaFuncAttributeMaxDynamicSharedMemorySize, SMEM_BYTES);

    // 1) fused prologue: router + out-zero + fp16 operand conversion
    pre_kernel<<<NB_PRE, 256>>>(x, gatew, w1, w2, sfc1, sfc2, sfc3, out);

    // 2) expert grouping
    scan_scatter_kernel<<<1, 512>>>();

    // 3) shared GEMM1 + MoE GEMM1 (merged)
    gemmA_mm<<<A_S1_BLOCKS + A_MOE_BLOCKS, 256, SMEM_BYTES>>>();

    // 4) shared GEMM2 + MoE GEMM2 (merged, atomic accumulate into out)
    gemmB_mm<<<B_S2_BLOCKS + B_MOE_BLOCKS, 256, SMEM_BYTES>>>(out);
}